// round 12
// baseline (speedup 1.0000x reference)
#include <cuda_runtime.h>
#include <cuda_fp16.h>
#include <cstdint>

#define KVOL 27
#define CIN  64
#define COUT 64
#define BM   128
#define FEAT_CAP 67108864LL   // halves (128 MiB static image)

__device__ int g_kmap_is64;
// fp16(rna) W image in fragment-pair layout (see prep_B): per k, 4 k-slice
// planes of 256 rows x 4 halves. 27 * 8KB = 216 KB (L1/L2-hot everywhere).
__device__ unsigned short g_Bimg[KVOL * CIN * COUT];
// fp16(rna) image of features, rebuilt every launch by prep_feat.
__device__ __half g_feat[FEAT_CAP];

__global__ void detect_kmap_dtype(const unsigned int* __restrict__ km) {
    // int64 little-endian values < 2^31 -> odd 32-bit words all zero.
    // int32 -> odd words are random indices, ~never all zero over 64 samples.
    int all_zero = 1;
    #pragma unroll 1
    for (int i = 0; i < 64; ++i)
        if (km[2 * i + 1] != 0u) { all_zero = 0; break; }
    g_kmap_is64 = all_zero;
}

__global__ void prep_feat(const float* __restrict__ f, long long n) {
    long long i = ((long long)blockIdx.x * blockDim.x + threadIdx.x) * 8;
    if (i + 8 <= n) {
        float4 v0 = *reinterpret_cast<const float4*>(f + i);
        float4 v1 = *reinterpret_cast<const float4*>(f + i + 4);
        __half2 h0 = __floats2half2_rn(v0.x, v0.y);
        __half2 h1 = __floats2half2_rn(v0.z, v0.w);
        __half2 h2 = __floats2half2_rn(v1.x, v1.y);
        __half2 h3 = __floats2half2_rn(v1.z, v1.w);
        uint4 o;
        o.x = *reinterpret_cast<unsigned*>(&h0);
        o.y = *reinterpret_cast<unsigned*>(&h1);
        o.z = *reinterpret_cast<unsigned*>(&h2);
        o.w = *reinterpret_cast<unsigned*>(&h3);
        *reinterpret_cast<uint4*>(&g_feat[i]) = o;
    } else {
        for (; i < n && i < FEAT_CAP; ++i) g_feat[i] = __float2half_rn(f[i]);
    }
}

// Fragment-pair B layout for mma.m16n8k16.row.col fp16 (same as R11):
//   thread (g=lane>>2, t4=lane&3), col n=co, k-slice ks needs halves
//   { W[16ks+2t4][co], [+1], [+8], [+9] } -> one 8B word at
//   plane ks (2KB), row = co*4 + t4.
__global__ void prep_B(const float* __restrict__ wk) {
    const int k = blockIdx.x;
    for (int i = threadIdx.x; i < CIN * COUT; i += blockDim.x) {
        const int ci = i >> 6;
        const int co = i & 63;
        const unsigned short h =
            __half_as_ushort(__float2half_rn(wk[k * 4096 + i]));
        const int ks = ci >> 4;
        const int kk = ci & 15;
        const int t4 = (kk & 7) >> 1;
        const int hi = ((kk >> 3) << 1) | (kk & 1);   // half slot in the word
        g_Bimg[k * 4096 + (ks * 256 + co * 4 + t4) * 4 + hi] = h;
    }
}

__device__ __forceinline__ void mma_f16(float c[4], const uint32_t a[4], const uint32_t b[2]) {
    asm volatile(
        "mma.sync.aligned.m16n8k16.row.col.f32.f16.f16.f32 "
        "{%0,%1,%2,%3}, {%4,%5,%6,%7}, {%8,%9}, {%0,%1,%2,%3};\n"
        : "+f"(c[0]), "+f"(c[1]), "+f"(c[2]), "+f"(c[3])
        : "r"(a[0]), "r"(a[1]), "r"(a[2]), "r"(a[3]),
          "r"(b[0]), "r"(b[1]));
}

__device__ __forceinline__ void ldsm_x4(uint32_t a[4], uint32_t addr) {
    asm volatile("ldmatrix.sync.aligned.m8n8.x4.shared.b16 {%0,%1,%2,%3}, [%4];"
                 : "=r"(a[0]), "=r"(a[1]), "=r"(a[2]), "=r"(a[3]) : "r"(addr));
}

// B fragment: 8B read-only global load (L1-hot image)
__device__ __forceinline__ void ldg_b(uint32_t b[2], const void* p) {
    asm volatile("ld.global.nc.v2.b32 {%0,%1}, [%2];"
                 : "=r"(b[0]), "=r"(b[1]) : "l"(p));
}

// cp.async 16B, L2-only (gather), zero-fill when sz==0 (masked rows)
__device__ __forceinline__ void cp16_cg_zfill(uint32_t smem, const void* g, int sz) {
    asm volatile("cp.async.cg.shared.global [%0], [%1], 16, %2;\n"
                 :: "r"(smem), "l"(g), "r"(sz) : "memory");
}

extern __shared__ char dyn_smem[];

// SMEM layout (bytes): 3 A stages 16KB @0/16384/32768, sIdx @49152.
#define A_BYTES   16384
#define OFF_IDX   49152
#define SMEM_TOTAL (OFF_IDX + BM * KVOL * 4)   // 62,976 B -> 3 CTA/SM

__global__ __launch_bounds__(128, 3)
void sparse_conv_f16(const long long* __restrict__ kmap64,
                     const int* __restrict__ kmap32,
                     const int* __restrict__ kmask,
                     float* __restrict__ out,
                     int n_pts)
{
    int* sIdx = (int*)(dyn_smem + OFF_IDX);
    const uint32_t sbase = (uint32_t)__cvta_generic_to_shared(dyn_smem);

    const int tid  = threadIdx.x;          // 0..127
    const int lane = tid & 31;
    const int warp = tid >> 5;             // 0..3  (M dimension)
    const int m0   = warp * 32;
    const int g    = lane >> 2;            // 0..7
    const int t4   = lane & 3;             // 0..3
    const long long blk0 = (long long)blockIdx.x * BM;
    const int is64 = g_kmap_is64;

    // ---- fused (mask ? idx : -1) for all 128 pts x 27 offsets, coalesced ----
    {
        const long long entry0    = blk0 * KVOL;
        const long long entry_end = (long long)n_pts * KVOL;
        #pragma unroll 1
        for (int j = 0; j < KVOL; ++j) {
            const long long e = entry0 + j * 128 + tid;
            int v = -1;
            if (e < entry_end && kmask[e]) {
                long long idx = is64 ? kmap64[e] : (long long)kmap32[e];
                if (idx < 0 || idx >= n_pts) idx = 0;   // never fault
                v = (int)idx;
            }
            sIdx[j * 128 + tid] = v;
        }
    }
    __syncthreads();

    // gather assignment: 8 lanes cover one 128B fp16 feature row (1 line)
    const int chunk  = tid & 7;            // 16B chunk within row
    const int rowgrp = tid >> 3;           // 0..15

    // A-only async stage fill (one cp.async group per call)
    auto issue = [&](int k, int stage) {
        const uint32_t ab = sbase + stage * A_BYTES;
        int idxs[8];
        #pragma unroll
        for (int r = 0; r < 8; ++r)
            idxs[r] = sIdx[(r * 16 + rowgrp) * KVOL + k];   // broadcast
        #pragma unroll
        for (int r = 0; r < 8; ++r) {
            const int row = r * 16 + rowgrp;
            const int v   = idxs[r];
            const long long i = (v >= 0) ? (long long)v : 0;
            cp16_cg_zfill(ab + row * 128 + ((chunk ^ (row & 7)) << 4),
                          g_feat + i * CIN + chunk * 8, (v >= 0) ? 16 : 0);
        }
        asm volatile("cp.async.commit_group;\n" ::: "memory");
    };

    float acc[2][8][4];
    #pragma unroll
    for (int mi = 0; mi < 2; ++mi)
        #pragma unroll
        for (int ni = 0; ni < 8; ++ni)
            #pragma unroll
            for (int j = 0; j < 4; ++j)
                acc[mi][ni][j] = 0.0f;

    issue(0, 0);
    issue(1, 1);

    // ldmatrix lane addressing (row-major A, 16B chunk swizzle c^(row&7))
    const int ldrow  = (lane & 7) + 8 * ((lane >> 3) & 1);
    const int ldcoff = lane >> 4;                   // 0 or 1
    const int brow   = g * 4 + t4;                  // B row base (ni=0)

    int stage = 0;   // stage of k
    #pragma unroll 1
    for (int k = 0; k < KVOL; ++k) {
        // stage k's group complete (allow the newest one to still be in flight)
        if (k + 1 < KVOL) {
            asm volatile("cp.async.wait_group 1;\n" ::: "memory");
        } else {
            asm volatile("cp.async.wait_group 0;\n" ::: "memory");
        }
        // One sync per k: admits stage k to all warps AND guarantees every
        // thread finished compute(k-1), so reissuing its buffer below is safe.
        __syncthreads();

        if (k + 2 < KVOL) {
            int ns = stage + 2; if (ns >= 3) ns -= 3;
            issue(k + 2, ns);
        }

        const uint32_t a_sm = sbase + stage * A_BYTES;
        const unsigned short* bk = g_Bimg + k * 4096;

        // ---- warp tile 32(M) x 64(N), K=64 in 4 slices of 16 ----
        #pragma unroll
        for (int ks = 0; ks < 4; ++ks) {
            uint32_t b[8][2];
            #pragma unroll
            for (int ni = 0; ni < 8; ++ni)
                ldg_b(b[ni], bk + (ks * 256 + ni * 32 + brow) * 4);
            uint32_t a[2][4];
            #pragma unroll
            for (int mi = 0; mi < 2; ++mi) {
                const int row = m0 + mi * 16 + ldrow;
                ldsm_x4(a[mi], a_sm + row * 128 +
                               (((2 * ks + ldcoff) ^ (row & 7)) << 4));
            }
            #pragma unroll
            for (int mi = 0; mi < 2; ++mi)
                #pragma unroll
                for (int ni = 0; ni < 8; ++ni)
                    mma_f16(acc[mi][ni], a[mi], b[ni]);
        }

        if (++stage == 3) stage = 0;
    }

    // ---- epilogue: c frag layout -> out[n, co] (fp32) ----
    #pragma unroll
    for (int mi = 0; mi < 2; ++mi) {
        const long long r0 = blk0 + m0 + mi * 16 + g;
        #pragma unroll
        for (int ni = 0; ni < 8; ++ni) {
            const int col = ni * 8 + t4 * 2;
            if (r0 < n_pts)
                *reinterpret_cast<float2*>(out + r0 * COUT + col) =
                    make_float2(acc[mi][ni][0], acc[mi][ni][1]);
            if (r0 + 8 < n_pts)
                *reinterpret_cast<float2*>(out + (r0 + 8) * COUT + col) =
                    make_float2(acc[mi][ni][2], acc[mi][ni][3]);
        }
    }
}

extern "C" void kernel_launch(void* const* d_in, const int* in_sizes, int n_in,
                              void* d_out, int out_size) {
    const float* features = (const float*)d_in[0];
    const float* wkernel  = (const float*)d_in[1];
    const void*  kmap     = d_in[2];
    const int*   kmask    = (const int*)d_in[3];
    float*       out      = (float*)d_out;

    long long nfeat = (long long)in_sizes[0];
    if (nfeat > FEAT_CAP) nfeat = FEAT_CAP;          // defensive
    int n_pts = (int)(nfeat / CIN);
    const int grid = (n_pts + BM - 1) / BM;

    cudaFuncSetAttribute(sparse_conv_f16,
                         cudaFuncAttributeMaxDynamicSharedMemorySize, SMEM_TOTAL);

    detect_kmap_dtype<<<1, 1>>>((const unsigned int*)kmap);
    prep_feat<<<(int)((nfeat / 8 + 255) / 256), 256>>>(features, nfeat);
    prep_B<<<KVOL, 128>>>(wkernel);
    sparse_conv_f16<<<grid, 128, SMEM_TOTAL>>>((const long long*)kmap,
                                               (const int*)kmap,
                                               kmask, out, n_pts);
}